// round 7
// baseline (speedup 1.0000x reference)
#include <cuda_runtime.h>

#define T_DIM 1024
#define O_DIM 512
#define D_DIM 256
#define H_DIM 512
#define M_DIM (T_DIM + O_DIM)   // 1536

// Scratch (no allocations allowed)
__device__ float g_A[M_DIM * H_DIM];   // rows 0..1023: ht ; rows 1024..1535: ho + b1
__device__ float g_u[M_DIM];           // g_A[m] . W2

typedef unsigned long long u64;

__device__ __forceinline__ u64 addx2(u64 a, u64 b) {
    u64 r; asm("add.rn.f32x2 %0,%1,%2;" : "=l"(r) : "l"(a), "l"(b)); return r;
}
__device__ __forceinline__ u64 fmax2(u64 a, u64 b, u64 c) {
    u64 r; asm("fma.rn.f32x2 %0,%1,%2,%3;" : "=l"(r) : "l"(a), "l"(b), "l"(c)); return r;
}

union F2U { float2 f; u64 u; };

__device__ __forceinline__ u64 pack2(float x, float y) {
    F2U t; t.f = make_float2(x, y); return t.u;
}
__device__ __forceinline__ u64 dup2(float v) {
    F2U t; t.f = make_float2(v, v); return t.u;
}

// ---------------------------------------------------------------------------
// Kernel 1: combined SGEMM with f32x2 packing along h.
//   m < 1024:  g_A[m][h] = sum_k z_t[m][k]   * W1[k][h]
//   m >= 1024: g_A[m][h] = sum_k z_o[m-T][k] * W1[256+k][h] + b1[h]
// Tiles: BM=64, BN=32, BK=16. 256 threads, each thread 2(m) x 4(h) outputs
// held as 4 packed f32x2 accumulators. A-operand staged DUPLICATED ((z,z))
// so FFMA2 needs no lane-dup MOVs. grid = 16 x 24 = 384 CTAs (2.6 waves).
// ---------------------------------------------------------------------------
__global__ __launch_bounds__(256) void gemm_kernel(
    const float* __restrict__ z_t, const float* __restrict__ z_o,
    const float* __restrict__ W1,  const float* __restrict__ b1)
{
    __shared__ __align__(16) u64 Zs[64][17];   // [m][k] dup pairs, pad->17 (odd)
    __shared__ __align__(16) u64 Ws[16][18];   // [k][h-pair], row 144B (16B align)

    const int tid = threadIdx.x;
    const int tx = tid & 7;          // jp0 = tx*2 (h-pairs)
    const int ty = tid >> 3;         // i0  = ty*2 (m rows)
    const int m0 = blockIdx.y * 64;
    const int h0 = blockIdx.x * 32;
    const bool is_o = (m0 >= T_DIM);
    const float* Z = is_o ? z_o : z_t;
    const int mrow0 = is_o ? (m0 - T_DIM) : m0;
    const int kbase = is_o ? D_DIM : 0;

    // staging mapping
    const int zm = tid >> 2;         // 0..63
    const int zk = (tid & 3) * 4;    // 0,4,8,12
    const int wk = tid >> 4;         // 0..15
    const int wc = tid & 15;         // h-pair col 0..15

    const float* zp = Z + (mrow0 + zm) * D_DIM + zk;
    const float* wp = W1 + (kbase + wk) * H_DIM + h0 + wc * 2;

    u64 acc00 = 0, acc01 = 0, acc10 = 0, acc11 = 0;

    float4 zr = *(const float4*)zp;
    float2 wr = *(const float2*)wp;

    for (int c = 0; c < 16; ++c) {
        Zs[zm][zk + 0] = dup2(zr.x);
        Zs[zm][zk + 1] = dup2(zr.y);
        Zs[zm][zk + 2] = dup2(zr.z);
        Zs[zm][zk + 3] = dup2(zr.w);
        Ws[wk][wc] = pack2(wr.x, wr.y);
        __syncthreads();
        if (c < 15) {
            zr = *(const float4*)(zp + (c + 1) * 16);
            wr = *(const float2*)(wp + (c + 1) * 16 * H_DIM);
        }
        #pragma unroll
        for (int k = 0; k < 16; ++k) {
            u64 a0 = Zs[ty * 2 + 0][k];
            u64 a1 = Zs[ty * 2 + 1][k];
            ulonglong2 b = *(const ulonglong2*)&Ws[k][tx * 2];
            acc00 = fmax2(a0, b.x, acc00);
            acc01 = fmax2(a0, b.y, acc01);
            acc10 = fmax2(a1, b.x, acc10);
            acc11 = fmax2(a1, b.y, acc11);
        }
        __syncthreads();
    }

    float4 bv = make_float4(0.f, 0.f, 0.f, 0.f);
    if (is_o) bv = *(const float4*)(b1 + h0 + tx * 4);

    F2U c00, c01, c10, c11;
    c00.u = acc00; c01.u = acc01; c10.u = acc10; c11.u = acc11;
    *(float4*)&g_A[(m0 + ty * 2 + 0) * H_DIM + h0 + tx * 4] =
        make_float4(c00.f.x + bv.x, c00.f.y + bv.y, c01.f.x + bv.z, c01.f.y + bv.w);
    *(float4*)&g_A[(m0 + ty * 2 + 1) * H_DIM + h0 + tx * 4] =
        make_float4(c10.f.x + bv.x, c10.f.y + bv.y, c11.f.x + bv.z, c11.f.y + bv.w);
}

// ---------------------------------------------------------------------------
// Kernel 2: g_u[m] = g_A[m] . W2   (one warp per row)
// ---------------------------------------------------------------------------
__global__ __launch_bounds__(256) void rowdot_kernel(const float* __restrict__ W2)
{
    const int warp = blockIdx.x * 8 + (threadIdx.x >> 5);
    const int lane = threadIdx.x & 31;
    const float* row = g_A + warp * H_DIM;
    float s = 0.f;
    #pragma unroll
    for (int q = 0; q < 4; ++q) {
        const int idx = q * 128 + lane * 4;
        float4 a = *(const float4*)(row + idx);
        float4 w = *(const float4*)(W2 + idx);
        s += a.x * w.x + a.y * w.y + a.z * w.z + a.w * w.w;
    }
    #pragma unroll
    for (int d = 16; d >= 1; d >>= 1) s += __shfl_xor_sync(0xFFFFFFFFu, s, d);
    if (lane == 0) g_u[warp] = s;
}

// ---------------------------------------------------------------------------
// Kernel 3: main abs-bilinear loop.
// out[t][o] = 0.505*(u[t]+u[T+o]) + 0.495 * sum_h |A[t][h]+A[T+o][h]| * w[h] + b2
// 64x64 tile, 256 threads (16x16), 4x4 per thread, h packed by 2 (f32x2).
// ROW-MAJOR smem tiles u64[64][33] (pad-33): staging STS.64 conflict-free,
// A-reads broadcast; B uses STRIDED j-blocking (j = tx+16r) so the 4 LDS.64
// per k hit 16 distinct banks (conflict-free) instead of 4-way-conflicted
// contiguous LDS.128.
// ---------------------------------------------------------------------------
__global__ __launch_bounds__(256) void cfm_main_kernel(
    const float* __restrict__ W2, const float* __restrict__ b2,
    float* __restrict__ out)
{
    __shared__ __align__(16) u64 As[64][33];   // [t-row][h-pair], pad->33 (odd)
    __shared__ __align__(16) u64 Bs[64][33];   // [o-row][h-pair]
    __shared__ u64 wsm[32];

    const int tid = threadIdx.x;
    const int tx = tid & 15, ty = tid >> 4;
    const int t0 = blockIdx.y * 64;
    const int o0 = blockIdx.x * 64;

    // staging: thread loads 16 consecutive floats (8 h-pairs) of one row
    const int srow = tid >> 2;           // 0..63
    const int pg   = (tid & 3) * 8;      // pair-group start: 0,8,16,24
    const float* Arow = g_A + (t0 + srow) * H_DIM + pg * 2;
    const float* Brow = g_A + (T_DIM + o0 + srow) * H_DIM + pg * 2;

    u64 acc[4][4] = {};

    float4 ra[4], rb[4];
    #pragma unroll
    for (int r = 0; r < 4; ++r) {
        ra[r] = *(const float4*)(Arow + r * 4);
        rb[r] = *(const float4*)(Brow + r * 4);
    }
    float2 wf = make_float2(0.f, 0.f);
    if (tid < 32) wf = *(const float2*)(W2 + tid * 2);

    const u64 ABSM = 0x7FFFFFFF7FFFFFFFULL;

    for (int c = 0; c < 8; ++c) {
        #pragma unroll
        for (int r = 0; r < 4; ++r) {
            As[srow][pg + r * 2 + 0] = pack2(ra[r].x, ra[r].y);
            As[srow][pg + r * 2 + 1] = pack2(ra[r].z, ra[r].w);
            Bs[srow][pg + r * 2 + 0] = pack2(rb[r].x, rb[r].y);
            Bs[srow][pg + r * 2 + 1] = pack2(rb[r].z, rb[r].w);
        }
        if (tid < 32) wsm[tid] = pack2(wf.x, wf.y);
        __syncthreads();
        if (c < 7) {
            const int off = (c + 1) * 64;   // 64 floats = 32 pairs per chunk
            #pragma unroll
            for (int r = 0; r < 4; ++r) {
                ra[r] = *(const float4*)(Arow + off + r * 4);
                rb[r] = *(const float4*)(Brow + off + r * 4);
            }
            if (tid < 32) wf = *(const float2*)(W2 + (c + 1) * 64 + tid * 2);
        }
        #pragma unroll 4
        for (int k = 0; k < 32; ++k) {
            u64 a2[4], bv[4];
            #pragma unroll
            for (int i = 0; i < 4; ++i) a2[i] = As[ty * 4 + i][k];
            #pragma unroll
            for (int r = 0; r < 4; ++r) bv[r] = Bs[tx + 16 * r][k];
            const u64 w2 = wsm[k];
            #pragma unroll
            for (int i = 0; i < 4; ++i)
                #pragma unroll
                for (int j = 0; j < 4; ++j) {
                    u64 s = addx2(a2[i], bv[j]);
                    s &= ABSM;                       // |.| both lanes (2x LOP3, alu pipe)
                    acc[i][j] = fmax2(s, w2, acc[i][j]);
                }
        }
        __syncthreads();
    }

    // epilogue (strided j: thread's columns are o0 + tx + 16r)
    const float b2v = b2[0];
    float ut[4], uo[4];
    #pragma unroll
    for (int i = 0; i < 4; ++i) ut[i] = g_u[t0 + ty * 4 + i];
    #pragma unroll
    for (int r = 0; r < 4; ++r) uo[r] = g_u[T_DIM + o0 + tx + 16 * r];

    #pragma unroll
    for (int i = 0; i < 4; ++i) {
        float* orow = out + (t0 + ty * 4 + i) * O_DIM + o0;
        #pragma unroll
        for (int r = 0; r < 4; ++r) {
            F2U cu; cu.u = acc[i][r];
            const float S = cu.f.x + cu.f.y;
            orow[tx + 16 * r] = 0.505f * (ut[i] + uo[r]) + 0.495f * S + b2v;
        }
    }
}

// ---------------------------------------------------------------------------
extern "C" void kernel_launch(void* const* d_in, const int* in_sizes, int n_in,
                              void* d_out, int out_size)
{
    const float* z_t = (const float*)d_in[0];   // [1024,256]
    const float* z_o = (const float*)d_in[1];   // [512,256]
    const float* W1  = (const float*)d_in[2];   // [512,512]
    const float* b1  = (const float*)d_in[3];   // [512]
    const float* W2  = (const float*)d_in[4];   // [512,1]
    const float* b2  = (const float*)d_in[5];   // [1]
    float* out = (float*)d_out;                 // [1024,512]

    (void)in_sizes; (void)n_in; (void)out_size;

    gemm_kernel<<<dim3(H_DIM / 32, M_DIM / 64), 256>>>(z_t, z_o, W1, b1);
    rowdot_kernel<<<M_DIM / 8, 256>>>(W2);
    cfm_main_kernel<<<dim3(O_DIM / 64, T_DIM / 64), 256>>>(W2, b2, out);
}

// round 10
// speedup vs baseline: 1.1461x; 1.1461x over previous
#include <cuda_runtime.h>

#define T_DIM 1024
#define O_DIM 512
#define D_DIM 256
#define H_DIM 512
#define M_DIM (T_DIM + O_DIM)   // 1536

// Scratch (no allocations allowed)
__device__ float g_A[M_DIM * H_DIM];   // rows 0..1023: ht ; rows 1024..1535: ho + b1
__device__ float g_u[M_DIM];           // g_A[m] . W2

typedef unsigned long long u64;

__device__ __forceinline__ u64 addx2(u64 a, u64 b) {
    u64 r; asm("add.rn.f32x2 %0,%1,%2;" : "=l"(r) : "l"(a), "l"(b)); return r;
}
__device__ __forceinline__ u64 fmax2(u64 a, u64 b, u64 c) {
    u64 r; asm("fma.rn.f32x2 %0,%1,%2,%3;" : "=l"(r) : "l"(a), "l"(b), "l"(c)); return r;
}

union F2U { float2 f; u64 u; };

__device__ __forceinline__ u64 pack2(float x, float y) {
    F2U t; t.f = make_float2(x, y); return t.u;
}

// ---------------------------------------------------------------------------
// Kernel 1: combined SGEMM (scalar FFMA, occupancy-oriented).
//   m < 1024:  g_A[m][h] = sum_k z_t[m][k]   * W1[k][h]
//   m >= 1024: g_A[m][h] = sum_k z_o[m-T][k] * W1[256+k][h] + b1[h]
// Tiles: BM=32, BN=64, BK=16. 128 threads, 4x4 per thread.
// grid = 8 x 48 = 384 CTAs, ~6.9KB smem, ~60 regs -> 4+ CTAs/SM resident.
// Zs rows padded to 36 floats (144B = 9*16B) so LDS.128 stays 16B-aligned.
// ---------------------------------------------------------------------------
__global__ __launch_bounds__(128) void gemm_kernel(
    const float* __restrict__ z_t, const float* __restrict__ z_o,
    const float* __restrict__ W1,  const float* __restrict__ b1)
{
    __shared__ __align__(16) float Zs[16][36];   // [k][m], pad->36 (16B-aligned rows)
    __shared__ __align__(16) float Ws[16][68];   // [k][h], pad->68 (16B-aligned rows)

    const int tid = threadIdx.x;
    const int tx = tid & 15;         // h: tx*4
    const int ty = tid >> 4;         // m: ty*4  (0..7 -> 32 rows)
    const int m0 = blockIdx.y * 32;
    const int h0 = blockIdx.x * 64;
    const bool is_o = (m0 >= T_DIM);
    const float* Z = is_o ? z_o : z_t;
    const int mrow0 = is_o ? (m0 - T_DIM) : m0;
    const int kbase = is_o ? D_DIM : 0;

    // staging mapping
    const int zm = tid >> 2;         // 0..31
    const int zk = (tid & 3) * 4;    // 0,4,8,12
    const int wk = tid >> 3;         // 0..15
    const int wh = (tid & 7) * 8;    // 0..56

    const float* zp = Z + (mrow0 + zm) * D_DIM + zk;
    const float* wp = W1 + (kbase + wk) * H_DIM + h0 + wh;

    float acc[4][4] = {};

    float4 zr = *(const float4*)zp;
    float4 wr0 = *(const float4*)wp;
    float4 wr1 = *(const float4*)(wp + 4);

    for (int c = 0; c < 16; ++c) {
        Zs[zk + 0][zm] = zr.x; Zs[zk + 1][zm] = zr.y;
        Zs[zk + 2][zm] = zr.z; Zs[zk + 3][zm] = zr.w;
        *(float4*)&Ws[wk][wh]     = wr0;
        *(float4*)&Ws[wk][wh + 4] = wr1;
        __syncthreads();
        if (c < 15) {
            zr  = *(const float4*)(zp + (c + 1) * 16);
            wr0 = *(const float4*)(wp + (c + 1) * 16 * H_DIM);
            wr1 = *(const float4*)(wp + (c + 1) * 16 * H_DIM + 4);
        }
        #pragma unroll
        for (int k = 0; k < 16; ++k) {
            float4 a = *(const float4*)&Zs[k][ty * 4];
            float4 b = *(const float4*)&Ws[k][tx * 4];
            float av[4] = {a.x, a.y, a.z, a.w};
            float bv[4] = {b.x, b.y, b.z, b.w};
            #pragma unroll
            for (int i = 0; i < 4; ++i)
                #pragma unroll
                for (int j = 0; j < 4; ++j)
                    acc[i][j] = fmaf(av[i], bv[j], acc[i][j]);
        }
        __syncthreads();
    }

    float bj[4] = {0.f, 0.f, 0.f, 0.f};
    if (is_o) {
        #pragma unroll
        for (int j = 0; j < 4; ++j) bj[j] = b1[h0 + tx * 4 + j];
    }
    #pragma unroll
    for (int i = 0; i < 4; ++i) {
        float4 v = make_float4(acc[i][0] + bj[0], acc[i][1] + bj[1],
                               acc[i][2] + bj[2], acc[i][3] + bj[3]);
        *(float4*)&g_A[(m0 + ty * 4 + i) * H_DIM + h0 + tx * 4] = v;
    }
}

// ---------------------------------------------------------------------------
// Kernel 2: g_u[m] = g_A[m] . W2   (one warp per row)
// ---------------------------------------------------------------------------
__global__ __launch_bounds__(256) void rowdot_kernel(const float* __restrict__ W2)
{
    const int warp = blockIdx.x * 8 + (threadIdx.x >> 5);
    const int lane = threadIdx.x & 31;
    const float* row = g_A + warp * H_DIM;
    float s = 0.f;
    #pragma unroll
    for (int q = 0; q < 4; ++q) {
        const int idx = q * 128 + lane * 4;
        float4 a = *(const float4*)(row + idx);
        float4 w = *(const float4*)(W2 + idx);
        s += a.x * w.x + a.y * w.y + a.z * w.z + a.w * w.w;
    }
    #pragma unroll
    for (int d = 16; d >= 1; d >>= 1) s += __shfl_xor_sync(0xFFFFFFFFu, s, d);
    if (lane == 0) g_u[warp] = s;
}

// ---------------------------------------------------------------------------
// Kernel 3: main abs-bilinear loop.
// out[t][o] = 0.505*(u[t]+u[T+o]) + 0.495 * sum_h |A[t][h]+A[T+o][h]| * w[h] + b2
// Tile 32(t) x 64(o), 128 threads, 4x4 per thread (o strided tx+16r),
// h packed by 2 (f32x2). Chunks of 16 h-pairs. grid = 8 x 32 = 256 CTAs,
// 13.2KB smem -> 3 CTAs/SM resident (12 warps) and all 148 SMs busy.
// ---------------------------------------------------------------------------
__global__ __launch_bounds__(128) void cfm_main_kernel(
    const float* __restrict__ W2, const float* __restrict__ b2,
    float* __restrict__ out)
{
    __shared__ __align__(16) u64 As[32][17];   // [t-row][h-pair], pad->17
    __shared__ __align__(16) u64 Bs[64][17];   // [o-row][h-pair]
    __shared__ u64 wsm[16];

    const int tid = threadIdx.x;
    const int tx = tid & 15;         // o: cols tx + 16r
    const int ty = tid >> 4;         // t: rows ty*4 + i  (0..7 -> 32 rows)
    const int t0 = blockIdx.y * 32;
    const int o0 = blockIdx.x * 64;

    // staging mapping (per 16-pair chunk = 32 floats per row)
    const int arow = tid >> 2;           // 0..31
    const int apg  = (tid & 3) * 4;      // pair offset 0,4,8,12 (8 floats)
    const int brow = tid >> 1;           // 0..63
    const int bpg  = (tid & 1) * 8;      // pair offset 0,8      (16 floats)
    const float* Ap = g_A + (t0 + arow) * H_DIM + apg * 2;
    const float* Bp = g_A + (T_DIM + o0 + brow) * H_DIM + bpg * 2;

    u64 acc[4][4] = {};

    float4 ra[2], rb[4];
    ra[0] = *(const float4*)(Ap + 0);
    ra[1] = *(const float4*)(Ap + 4);
    #pragma unroll
    for (int r = 0; r < 4; ++r) rb[r] = *(const float4*)(Bp + r * 4);
    float2 wf = make_float2(0.f, 0.f);
    if (tid < 16) wf = *(const float2*)(W2 + tid * 2);

    const u64 ABSM = 0x7FFFFFFF7FFFFFFFULL;

    for (int c = 0; c < 16; ++c) {
        As[arow][apg + 0] = pack2(ra[0].x, ra[0].y);
        As[arow][apg + 1] = pack2(ra[0].z, ra[0].w);
        As[arow][apg + 2] = pack2(ra[1].x, ra[1].y);
        As[arow][apg + 3] = pack2(ra[1].z, ra[1].w);
        #pragma unroll
        for (int r = 0; r < 4; ++r) {
            Bs[brow][bpg + r * 2 + 0] = pack2(rb[r].x, rb[r].y);
            Bs[brow][bpg + r * 2 + 1] = pack2(rb[r].z, rb[r].w);
        }
        if (tid < 16) wsm[tid] = pack2(wf.x, wf.y);
        __syncthreads();
        if (c < 15) {
            const int off = (c + 1) * 32;   // 32 floats = 16 pairs per chunk
            ra[0] = *(const float4*)(Ap + off + 0);
            ra[1] = *(const float4*)(Ap + off + 4);
            #pragma unroll
            for (int r = 0; r < 4; ++r) rb[r] = *(const float4*)(Bp + off + r * 4);
            if (tid < 16) wf = *(const float2*)(W2 + (c + 1) * 32 + tid * 2);
        }
        #pragma unroll 8
        for (int k = 0; k < 16; ++k) {
            u64 a2[4], bv[4];
            #pragma unroll
            for (int i = 0; i < 4; ++i) a2[i] = As[ty * 4 + i][k];
            #pragma unroll
            for (int r = 0; r < 4; ++r) bv[r] = Bs[tx + 16 * r][k];
            const u64 w2 = wsm[k];
            #pragma unroll
            for (int i = 0; i < 4; ++i)
                #pragma unroll
                for (int j = 0; j < 4; ++j) {
                    u64 s = addx2(a2[i], bv[j]);
                    s &= ABSM;                       // |.| both lanes (2x LOP3, alu pipe)
                    acc[i][j] = fmax2(s, w2, acc[i][j]);
                }
        }
        __syncthreads();
    }

    // epilogue (thread's columns are o0 + tx + 16r)
    const float b2v = b2[0];
    float ut[4], uo[4];
    #pragma unroll
    for (int i = 0; i < 4; ++i) ut[i] = g_u[t0 + ty * 4 + i];
    #pragma unroll
    for (int r = 0; r < 4; ++r) uo[r] = g_u[T_DIM + o0 + tx + 16 * r];

    #pragma unroll
    for (int i = 0; i < 4; ++i) {
        float* orow = out + (t0 + ty * 4 + i) * O_DIM + o0;
        #pragma unroll
        for (int r = 0; r < 4; ++r) {
            F2U cu; cu.u = acc[i][r];
            const float S = cu.f.x + cu.f.y;
            orow[tx + 16 * r] = 0.505f * (ut[i] + uo[r]) + 0.495f * S + b2v;
        }
    }
}

// ---------------------------------------------------------------------------
extern "C" void kernel_launch(void* const* d_in, const int* in_sizes, int n_in,
                              void* d_out, int out_size)
{
    const float* z_t = (const float*)d_in[0];   // [1024,256]
    const float* z_o = (const float*)d_in[1];   // [512,256]
    const float* W1  = (const float*)d_in[2];   // [512,512]
    const float* b1  = (const float*)d_in[3];   // [512]
    const float* W2  = (const float*)d_in[4];   // [512,1]
    const float* b2  = (const float*)d_in[5];   // [1]
    float* out = (float*)d_out;                 // [1024,512]

    (void)in_sizes; (void)n_in; (void)out_size;

    gemm_kernel<<<dim3(H_DIM / 64, M_DIM / 32), 128>>>(z_t, z_o, W1, b1);
    rowdot_kernel<<<M_DIM / 8, 256>>>(W2);
    cfm_main_kernel<<<dim3(O_DIM / 64, T_DIM / 32), 128>>>(W2, b2, out);
}